// round 4
// baseline (speedup 1.0000x reference)
#include <cuda_runtime.h>

#define N_NODES 20000
#define FMD 128
#define NH 8
#define OCD 128
#define N_EDGE 160000
#define ETOT 180000           /* E + self loops */
#define CIRCN 504
#define MIRN 19496            /* N - CIRC */
#define PQ 9825984            /* CIRC * MIRN */
#define HCOLS 1024            /* H * FM */

#define BM 128
#define BN 128
#define BKC 64
#define SST 68                /* smem K-stride in floats (68*4B = 17*16B) */
#define GEMM_SMEM ((BM + BN) * SST * 4)

// ---------------- scratch (device globals; no runtime allocation) ----------
__device__ float    g_h[(size_t)N_NODES * HCOLS];   // y buffer, 81.92 MB
__device__ float    g_s[N_NODES * NH];
__device__ float    g_d[N_NODES * NH];
__device__ unsigned g_menc[N_NODES * NH];
__device__ float    g_den[N_NODES * NH];
__device__ float    g_e[(size_t)ETOT * NH];
__device__ int      g_deg[N_NODES];
__device__ int      g_off[N_NODES + 1];
__device__ int      g_cur[N_NODES];
__device__ int      g_srcS[ETOT];
__device__ int      g_eidS[ETOT];
__device__ int      g_srcC[ETOT];
__device__ int      g_dstC[ETOT];
__device__ int      g_is64;
__device__ float    g_x1[N_NODES * FMD];
__device__ float    g_x2[N_NODES * FMD];
__device__ float    g_As[FMD * NH];   // folded attention vectors
__device__ float    g_Ad[FMD * NH];

// ordered-uint encoding for float atomicMax
__device__ __forceinline__ unsigned fenc(float f) {
    unsigned u = __float_as_uint(f);
    return (u & 0x80000000u) ? ~u : (u | 0x80000000u);
}
__device__ __forceinline__ float fdec(unsigned u) {
    return (u & 0x80000000u) ? __uint_as_float(u & 0x7FFFFFFFu)
                             : __uint_as_float(~u);
}

// packed f32x2 FMA (Blackwell FFMA2): acc = a*b + acc elementwise on pairs
__device__ __forceinline__ void ffma2(unsigned long long& acc,
                                      unsigned long long a,
                                      unsigned long long b) {
    asm("fma.rn.f32x2 %0, %1, %2, %0;" : "+l"(acc) : "l"(a), "l"(b));
}
__device__ __forceinline__ float pairsum(unsigned long long v) {
    float lo = __uint_as_float((unsigned)(v & 0xffffffffull));
    float hi = __uint_as_float((unsigned)(v >> 32));
    return lo + hi;
}

// ---------------- edge-index dtype detect + decode -------------------------
__global__ void k_detect(const int* __restrict__ ei32) {
    int allz = 1;
    #pragma unroll
    for (int i = 1; i < 32; i += 2)
        if (ei32[i] != 0) allz = 0;
    g_is64 = allz;
}

__global__ void k_decode(const void* __restrict__ ei) {
    int i = blockIdx.x * 256 + threadIdx.x;
    if (i >= ETOT) return;
    int src, dst;
    if (i < N_EDGE) {
        if (g_is64) {
            const long long* p = (const long long*)ei;
            src = (int)p[i];
            dst = (int)p[N_EDGE + i];
        } else {
            const int* p = (const int*)ei;
            src = p[i];
            dst = p[N_EDGE + i];
        }
    } else {
        src = dst = i - N_EDGE;
    }
    g_srcC[i] = src;
    g_dstC[i] = dst;
}

// ---------------- CSR build ------------------------------------------------
__global__ void k_zero_deg() {
    int i = blockIdx.x * 256 + threadIdx.x;
    if (i < N_NODES) g_deg[i] = 0;
}

__global__ void k_count() {
    int i = blockIdx.x * 256 + threadIdx.x;
    if (i >= ETOT) return;
    atomicAdd(&g_deg[g_dstC[i]], 1);
}

__global__ void __launch_bounds__(1024) k_scan() {
    __shared__ int sh[1024];
    __shared__ int carry;
    int t = threadIdx.x;
    if (t == 0) carry = 0;
    __syncthreads();
    for (int base = 0; base < N_NODES; base += 1024) {
        int i = base + t;
        int v = (i < N_NODES) ? g_deg[i] : 0;
        sh[t] = v;
        __syncthreads();
        for (int s = 1; s < 1024; s <<= 1) {
            int tmp = (t >= s) ? sh[t - s] : 0;
            __syncthreads();
            sh[t] += tmp;
            __syncthreads();
        }
        int excl = carry + sh[t] - v;
        if (i < N_NODES) { g_off[i] = excl; g_cur[i] = excl; }
        __syncthreads();
        if (t == 0) carry += sh[1023];
        __syncthreads();
    }
    if (t == 0) g_off[N_NODES] = carry;
}

__global__ void k_scatter() {
    int i = blockIdx.x * 256 + threadIdx.x;
    if (i >= ETOT) return;
    int pos = atomicAdd(&g_cur[g_dstC[i]], 1);
    g_srcS[pos] = g_srcC[i];
    g_eidS[pos] = i;
}

// ---------------- folded attention: As[k,h] = sum_f W[k,h*128+f]*as[h,f] ---
__global__ void __launch_bounds__(128) k_fold(
    const float* __restrict__ W,
    const float* __restrict__ as, const float* __restrict__ ad)
{
    int kh = blockIdx.x;            // 0..1023
    int k = kh >> 3, h = kh & 7;
    int t = threadIdx.x;            // f
    float wv = W[(size_t)k * HCOLS + h * FMD + t];
    float sa = wv * as[h * FMD + t];
    float sd = wv * ad[h * FMD + t];
    __shared__ float sh[8];
    int lane = t & 31, wid = t >> 5;
    #pragma unroll
    for (int o = 16; o; o >>= 1) {
        sa += __shfl_xor_sync(0xffffffffu, sa, o);
        sd += __shfl_xor_sync(0xffffffffu, sd, o);
    }
    if (lane == 0) { sh[wid] = sa; sh[4 + wid] = sd; }
    __syncthreads();
    if (t == 0) {
        g_As[k * NH + h] = sh[0] + sh[1] + sh[2] + sh[3];
        g_Ad[k * NH + h] = sh[4] + sh[5] + sh[6] + sh[7];
    }
}

// ---------------- s,d = x @ As / x @ Ad  (per node) ------------------------
__global__ void __launch_bounds__(64) k_sd2(const float* __restrict__ Xext, int xsel) {
    const float* X = (xsel == 1) ? g_x1 : Xext;
    int n = blockIdx.x;
    int w = threadIdx.x >> 5, lane = threadIdx.x & 31;
    const float* xr = X + (size_t)n * FMD;
    const float* Av = (w == 0) ? g_As : g_Ad;
    float part[NH] = {};
    #pragma unroll
    for (int kk = 0; kk < 4; kk++) {
        int k = lane + kk * 32;
        float xv = xr[k];
        #pragma unroll
        for (int h = 0; h < NH; h++)
            part[h] += xv * Av[k * NH + h];
    }
    #pragma unroll
    for (int h = 0; h < NH; h++) {
        float v = part[h];
        #pragma unroll
        for (int o = 16; o; o >>= 1)
            v += __shfl_xor_sync(0xffffffffu, v, o);
        part[h] = v;
    }
    if (lane == 0) {
        float* o = (w == 0) ? g_s : g_d;
        #pragma unroll
        for (int h = 0; h < NH; h++) o[n * NH + h] = part[h];
    }
}

// ---------------- softmax pieces -------------------------------------------
__global__ void k_initmd() {
    int i = blockIdx.x * 256 + threadIdx.x;
    if (i < N_NODES * NH) { g_menc[i] = 0u; g_den[i] = 0.f; }
}

__global__ void k_emax() {
    int idx = blockIdx.x * 256 + threadIdx.x;
    if (idx >= ETOT * NH) return;
    int e = idx >> 3, hh = idx & 7;
    int src = g_srcC[e], dst = g_dstC[e];
    float v = g_s[src * NH + hh] + g_d[dst * NH + hh];
    v = (v > 0.f) ? v : 0.2f * v;
    g_e[idx] = v;
    atomicMax(&g_menc[dst * NH + hh], fenc(v));
}

__global__ void k_eexp() {
    int idx = blockIdx.x * 256 + threadIdx.x;
    if (idx >= ETOT * NH) return;
    int e = idx >> 3, hh = idx & 7;
    int dst = g_dstC[e];
    float m = fdec(g_menc[dst * NH + hh]);
    float ee = expf(g_e[idx] - m);
    g_e[idx] = ee;
    atomicAdd(&g_den[dst * NH + hh], ee);
}

// ---------------- aggregate x rows: y[n,h,f] = sum_e alpha[e,h] X[src,f] ---
__global__ void __launch_bounds__(128) k_aggx(const float* __restrict__ Xext, int xsel) {
    const float* X = (xsel == 1) ? g_x1 : Xext;
    int n = blockIdx.x;
    int f = threadIdx.x;
    float inv[NH];
    #pragma unroll
    for (int h = 0; h < NH; h++)
        inv[h] = 1.f / (g_den[n * NH + h] + 1e-16f);
    float acc[NH] = {};
    int e0 = g_off[n], e1 = g_off[n + 1];
    for (int j = e0; j < e1; j++) {
        int s   = g_srcS[j];
        int eid = g_eidS[j];
        float xv = X[(size_t)s * FMD + f];
        const float* er = g_e + (size_t)eid * NH;
        #pragma unroll
        for (int h = 0; h < NH; h++)
            acc[h] += er[h] * xv;
    }
    float* yr = g_h + (size_t)n * HCOLS + f;
    #pragma unroll
    for (int h = 0; h < NH; h++)
        yr[h * FMD] = acc[h] * inv[h];
}

// ---------------- unified FFMA2 GEMM ---------------------------------------
// C[M,Nn] = A[M,K] * B'[K,Nn]
// ASEL : 0 = ext A, 1 = g_h, 2 = dual [g_x1 | g_x2] along K (stride 128 each)
// BMODE: 0 = NT (B is [Nn,K] row-major, K contiguous)
//        1 = W-permuted NN: B'[kk][f] = W[kk&127][ (kk>>7)*128 + f ]
// MODE : 0 = plain store, 1 = +bias, route circ/mir into d_out, 2 = *0.125+bias+relu -> g_x1/g_x2
template <int ASEL, int BMODE, int MODE>
__global__ void __launch_bounds__(256, 1) gemm2(
    const float* __restrict__ A, const float* __restrict__ B,
    const float* __restrict__ bias, float* __restrict__ C,
    int M, int Nn, int K, int osel)
{
    extern __shared__ float smem[];
    float* sA = smem;              // [BM][SST]
    float* sB = smem + BM * SST;   // [BN][SST] (K-major)
    int tid = threadIdx.x;
    int tx = tid & 15, ty = tid >> 4;
    int m0 = blockIdx.x * BM, n0 = blockIdx.y * BN;

    const float* Ap = (ASEL == 1) ? g_h : A;

    unsigned long long acc[8][8];
    #pragma unroll
    for (int i = 0; i < 8; i++)
        #pragma unroll
        for (int j = 0; j < 8; j++) acc[i][j] = 0ull;

    for (int kc = 0; kc < K; kc += BKC) {
        // ---- stage A: rows K-contiguous ----
        #pragma unroll
        for (int p = 0; p < 8; p++) {
            int r  = p * 16 + (tid >> 4);
            int kq = (tid & 15) * 4;
            float4 v = make_float4(0.f, 0.f, 0.f, 0.f);
            int m = m0 + r;
            if (m < M) {
                if (ASEL == 2) {
                    int kg = kc + kq;
                    const float* src = (kg < FMD)
                        ? (g_x1 + (size_t)m * FMD + kg)
                        : (g_x2 + (size_t)m * FMD + (kg - FMD));
                    v = *(const float4*)src;
                } else {
                    v = *(const float4*)(Ap + (size_t)m * K + kc + kq);
                }
            }
            *(float4*)&sA[r * SST + kq] = v;
        }
        // ---- stage B K-major ----
        if (BMODE == 1) {
            // B'[gk][col] = W[gk&127][ (gk>>7)*128 + col ]; Nn == 128
            int col = tid & 127;
            int kh  = (tid >> 7) * 32;
            #pragma unroll
            for (int q = 0; q < 8; q++) {
                int kb = kh + q * 4;
                float4 v;
                float* dstp = &sB[col * SST + kb];
                int gk = kc + kb;
                const float* w0 = B + (size_t)(( (gk + 0) & 127)) * HCOLS + (((gk + 0) >> 7) * FMD) + col;
                const float* w1 = B + (size_t)(( (gk + 1) & 127)) * HCOLS + (((gk + 1) >> 7) * FMD) + col;
                const float* w2 = B + (size_t)(( (gk + 2) & 127)) * HCOLS + (((gk + 2) >> 7) * FMD) + col;
                const float* w3 = B + (size_t)(( (gk + 3) & 127)) * HCOLS + (((gk + 3) >> 7) * FMD) + col;
                v.x = *w0; v.y = *w1; v.z = *w2; v.w = *w3;
                *(float4*)dstp = v;
            }
        } else {
            #pragma unroll
            for (int p = 0; p < 8; p++) {
                int colr = p * 16 + (tid >> 4);
                int kq   = (tid & 15) * 4;
                float4 v = make_float4(0.f, 0.f, 0.f, 0.f);
                if (n0 + colr < Nn)
                    v = *(const float4*)(B + (size_t)(n0 + colr) * K + kc + kq);
                *(float4*)&sB[colr * SST + kq] = v;
            }
        }
        __syncthreads();

        // ---- compute: K-paired FFMA2, 8x8 microtile ----
        #pragma unroll
        for (int k4 = 0; k4 < 16; k4++) {
            int kk = k4 * 4;
            ulonglong2 bb[8];
            #pragma unroll
            for (int j = 0; j < 8; j++)
                bb[j] = *(const ulonglong2*)&sB[(tx + 16 * j) * SST + kk];
            #pragma unroll
            for (int i = 0; i < 8; i++) {
                ulonglong2 aa = *(const ulonglong2*)&sA[(ty * 8 + i) * SST + kk];
                #pragma unroll
                for (int j = 0; j < 8; j++) {
                    ffma2(acc[i][j], aa.x, bb[j].x);
                    ffma2(acc[i][j], aa.y, bb[j].y);
                }
            }
        }
        __syncthreads();
    }

    // ---- epilogue ----
    #pragma unroll
    for (int i = 0; i < 8; i++) {
        int m = m0 + ty * 8 + i;
        if (m >= M) continue;
        #pragma unroll
        for (int j = 0; j < 8; j++) {
            int col = n0 + tx + 16 * j;
            float v = pairsum(acc[i][j]);
            if (MODE == 0) {
                if (col < Nn)
                    C[(size_t)m * Nn + col] = v;
            } else if (MODE == 1) {
                v += bias[col];
                float* base = (m < CIRCN)
                    ? (C + PQ + (size_t)m * OCD)
                    : (C + PQ + (size_t)CIRCN * OCD + (size_t)(m - CIRCN) * OCD);
                base[col] = v;
            } else {
                v = fmaxf(v * 0.125f + bias[col], 0.f);
                float* o = (osel == 1) ? g_x1 : g_x2;
                o[(size_t)m * FMD + col] = v;
            }
        }
    }
}

// ---------------- launch ---------------------------------------------------
extern "C" void kernel_launch(void* const* d_in, const int* in_sizes, int n_in,
                              void* d_out, int out_size)
{
    const float* x   = (const float*)d_in[0];
    const void*  ei  = d_in[1];
    const float* W1  = (const float*)d_in[2];
    const float* as1 = (const float*)d_in[3];
    const float* ad1 = (const float*)d_in[4];
    const float* b1  = (const float*)d_in[5];
    const float* W2  = (const float*)d_in[6];
    const float* as2 = (const float*)d_in[7];
    const float* ad2 = (const float*)d_in[8];
    const float* b2  = (const float*)d_in[9];
    const float* Wc  = (const float*)d_in[10];
    const float* bc  = (const float*)d_in[11];
    float* out = (float*)d_out;

    cudaFuncSetAttribute(gemm2<1, 1, 2>, cudaFuncAttributeMaxDynamicSharedMemorySize, GEMM_SMEM);
    cudaFuncSetAttribute(gemm2<2, 0, 1>, cudaFuncAttributeMaxDynamicSharedMemorySize, GEMM_SMEM);
    cudaFuncSetAttribute(gemm2<0, 0, 0>, cudaFuncAttributeMaxDynamicSharedMemorySize, GEMM_SMEM);

    // edge decode + CSR
    k_detect<<<1, 1>>>((const int*)ei);
    k_decode<<<(ETOT + 255) / 256, 256>>>(ei);
    k_zero_deg<<<(N_NODES + 255) / 256, 256>>>();
    k_count<<<(ETOT + 255) / 256, 256>>>();
    k_scan<<<1, 1024>>>();
    k_scatter<<<(ETOT + 255) / 256, 256>>>();

    int gEH = (ETOT * NH + 255) / 256;
    int gMD = (N_NODES * NH + 255) / 256;
    dim3 gOut((N_NODES + BM - 1) / BM, 1);

    // ---- layer 1 ----
    k_fold<<<HCOLS, 128>>>(W1, as1, ad1);
    k_sd2<<<N_NODES, 64>>>(x, 0);
    k_initmd<<<gMD, 256>>>();
    k_emax<<<gEH, 256>>>();
    k_eexp<<<gEH, 256>>>();
    k_aggx<<<N_NODES, 128>>>(x, 0);
    gemm2<1, 1, 2><<<gOut, 256, GEMM_SMEM>>>(nullptr, W1, b1, nullptr,
                                             N_NODES, FMD, HCOLS, 1);

    // ---- layer 2 ----
    k_fold<<<HCOLS, 128>>>(W2, as2, ad2);
    k_sd2<<<N_NODES, 64>>>(nullptr, 1);
    k_initmd<<<gMD, 256>>>();
    k_emax<<<gEH, 256>>>();
    k_eexp<<<gEH, 256>>>();
    k_aggx<<<N_NODES, 128>>>(nullptr, 1);
    gemm2<1, 1, 2><<<gOut, 256, GEMM_SMEM>>>(nullptr, W2, b2, nullptr,
                                             N_NODES, FMD, HCOLS, 2);

    // ---- classifier: emb[n,o] = [x1|x2][n] . Wc[o,:] + bc[o] ----
    gemm2<2, 0, 1><<<gOut, 256, GEMM_SMEM>>>(nullptr, Wc, bc, out,
                                             N_NODES, OCD, 2 * FMD, 0);

    // ---- P = circ @ mir^T ----
    const float* circ = out + PQ;
    const float* mir  = out + PQ + (size_t)CIRCN * OCD;
    dim3 gP((CIRCN + BM - 1) / BM, (MIRN + BN - 1) / BN);
    gemm2<0, 0, 0><<<gP, 256, GEMM_SMEM>>>(circ, mir, nullptr, out,
                                           CIRCN, MIRN, FMD, 0);
}

// round 5
// speedup vs baseline: 1.8654x; 1.8654x over previous
#include <cuda_runtime.h>

#define N_NODES 20000
#define FMD 128
#define NH 8
#define OCD 128
#define N_EDGE 160000
#define ETOT 180000           /* E + self loops */
#define CIRCN 504
#define MIRN 19496            /* N - CIRC */
#define PQ 9825984            /* CIRC * MIRN */
#define HCOLS 1024            /* H * FM */

#define BM 128
#define BN 128
#define BK 32
#define SAST 36               /* sA row stride (floats): bank = lane%32, conflict-free */
#define SBST 136              /* sB k-row stride (floats): bank = 8k+n, conflict-free */

// ---------------- scratch (device globals; no runtime allocation) ----------
__device__ float    g_h[(size_t)N_NODES * HCOLS];   // y buffer
__device__ float    g_s[N_NODES * NH];
__device__ float    g_d[N_NODES * NH];
__device__ unsigned g_menc[N_NODES * NH];
__device__ float    g_den[N_NODES * NH];
__device__ float    g_e[(size_t)ETOT * NH];
__device__ int      g_deg[N_NODES];
__device__ int      g_off[N_NODES + 1];
__device__ int      g_cur[N_NODES];
__device__ int      g_srcS[ETOT];
__device__ int      g_eidS[ETOT];
__device__ int      g_srcC[ETOT];
__device__ int      g_dstC[ETOT];
__device__ int      g_is64;
__device__ float    g_x1[N_NODES * FMD];
__device__ float    g_x2[N_NODES * FMD];
__device__ float    g_As[FMD * NH];
__device__ float    g_Ad[FMD * NH];

// ordered-uint encoding for float atomicMax
__device__ __forceinline__ unsigned fenc(float f) {
    unsigned u = __float_as_uint(f);
    return (u & 0x80000000u) ? ~u : (u | 0x80000000u);
}
__device__ __forceinline__ float fdec(unsigned u) {
    return (u & 0x80000000u) ? __uint_as_float(u & 0x7FFFFFFFu)
                             : __uint_as_float(~u);
}

// fp32 -> tf32 (round to nearest)
__device__ __forceinline__ unsigned f2tf(float f) {
    unsigned r;
    asm("cvt.rna.tf32.f32 %0, %1;" : "=r"(r) : "f"(f));
    return r;
}

// m16n8k8 tf32 MMA, fp32 accumulate
__device__ __forceinline__ void mma_tf32(float* d, const unsigned* a, const unsigned* b) {
    asm("mma.sync.aligned.m16n8k8.row.col.f32.tf32.tf32.f32 "
        "{%0,%1,%2,%3}, {%4,%5,%6,%7}, {%8,%9}, {%0,%1,%2,%3};"
        : "+f"(d[0]), "+f"(d[1]), "+f"(d[2]), "+f"(d[3])
        : "r"(a[0]), "r"(a[1]), "r"(a[2]), "r"(a[3]), "r"(b[0]), "r"(b[1]));
}

// ---------------- edge-index dtype detect + decode -------------------------
__global__ void k_detect(const int* __restrict__ ei32) {
    int allz = 1;
    #pragma unroll
    for (int i = 1; i < 32; i += 2)
        if (ei32[i] != 0) allz = 0;
    g_is64 = allz;
}

__global__ void k_decode(const void* __restrict__ ei) {
    int i = blockIdx.x * 256 + threadIdx.x;
    if (i >= ETOT) return;
    int src, dst;
    if (i < N_EDGE) {
        if (g_is64) {
            const long long* p = (const long long*)ei;
            src = (int)p[i];
            dst = (int)p[N_EDGE + i];
        } else {
            const int* p = (const int*)ei;
            src = p[i];
            dst = p[N_EDGE + i];
        }
    } else {
        src = dst = i - N_EDGE;
    }
    g_srcC[i] = src;
    g_dstC[i] = dst;
}

// ---------------- CSR build ------------------------------------------------
__global__ void k_zero_deg() {
    int i = blockIdx.x * 256 + threadIdx.x;
    if (i < N_NODES) g_deg[i] = 0;
}

__global__ void k_count() {
    int i = blockIdx.x * 256 + threadIdx.x;
    if (i >= ETOT) return;
    atomicAdd(&g_deg[g_dstC[i]], 1);
}

__global__ void __launch_bounds__(1024) k_scan() {
    __shared__ int sh[1024];
    __shared__ int carry;
    int t = threadIdx.x;
    if (t == 0) carry = 0;
    __syncthreads();
    for (int base = 0; base < N_NODES; base += 1024) {
        int i = base + t;
        int v = (i < N_NODES) ? g_deg[i] : 0;
        sh[t] = v;
        __syncthreads();
        for (int s = 1; s < 1024; s <<= 1) {
            int tmp = (t >= s) ? sh[t - s] : 0;
            __syncthreads();
            sh[t] += tmp;
            __syncthreads();
        }
        int excl = carry + sh[t] - v;
        if (i < N_NODES) { g_off[i] = excl; g_cur[i] = excl; }
        __syncthreads();
        if (t == 0) carry += sh[1023];
        __syncthreads();
    }
    if (t == 0) g_off[N_NODES] = carry;
}

__global__ void k_scatter() {
    int i = blockIdx.x * 256 + threadIdx.x;
    if (i >= ETOT) return;
    int pos = atomicAdd(&g_cur[g_dstC[i]], 1);
    g_srcS[pos] = g_srcC[i];
    g_eidS[pos] = i;
}

// ---------------- folded attention: As[k,h] = sum_f W[k,h*128+f]*as[h,f] ---
__global__ void __launch_bounds__(128) k_fold(
    const float* __restrict__ W,
    const float* __restrict__ as, const float* __restrict__ ad)
{
    int kh = blockIdx.x;
    int k = kh >> 3, h = kh & 7;
    int t = threadIdx.x;
    float wv = W[(size_t)k * HCOLS + h * FMD + t];
    float sa = wv * as[h * FMD + t];
    float sd = wv * ad[h * FMD + t];
    __shared__ float sh[8];
    int lane = t & 31, wid = t >> 5;
    #pragma unroll
    for (int o = 16; o; o >>= 1) {
        sa += __shfl_xor_sync(0xffffffffu, sa, o);
        sd += __shfl_xor_sync(0xffffffffu, sd, o);
    }
    if (lane == 0) { sh[wid] = sa; sh[4 + wid] = sd; }
    __syncthreads();
    if (t == 0) {
        g_As[k * NH + h] = sh[0] + sh[1] + sh[2] + sh[3];
        g_Ad[k * NH + h] = sh[4] + sh[5] + sh[6] + sh[7];
    }
}

// ---------------- s,d = x @ As / x @ Ad ------------------------------------
__global__ void __launch_bounds__(64) k_sd2(const float* __restrict__ Xext, int xsel) {
    const float* X = (xsel == 1) ? g_x1 : Xext;
    int n = blockIdx.x;
    int w = threadIdx.x >> 5, lane = threadIdx.x & 31;
    const float* xr = X + (size_t)n * FMD;
    const float* Av = (w == 0) ? g_As : g_Ad;
    float part[NH] = {};
    #pragma unroll
    for (int kk = 0; kk < 4; kk++) {
        int k = lane + kk * 32;
        float xv = xr[k];
        #pragma unroll
        for (int h = 0; h < NH; h++)
            part[h] += xv * Av[k * NH + h];
    }
    #pragma unroll
    for (int h = 0; h < NH; h++) {
        float v = part[h];
        #pragma unroll
        for (int o = 16; o; o >>= 1)
            v += __shfl_xor_sync(0xffffffffu, v, o);
        part[h] = v;
    }
    if (lane == 0) {
        float* o = (w == 0) ? g_s : g_d;
        #pragma unroll
        for (int h = 0; h < NH; h++) o[n * NH + h] = part[h];
    }
}

// ---------------- softmax pieces -------------------------------------------
__global__ void k_initmd() {
    int i = blockIdx.x * 256 + threadIdx.x;
    if (i < N_NODES * NH) { g_menc[i] = 0u; g_den[i] = 0.f; }
}

__global__ void k_emax() {
    int idx = blockIdx.x * 256 + threadIdx.x;
    if (idx >= ETOT * NH) return;
    int e = idx >> 3, hh = idx & 7;
    int src = g_srcC[e], dst = g_dstC[e];
    float v = g_s[src * NH + hh] + g_d[dst * NH + hh];
    v = (v > 0.f) ? v : 0.2f * v;
    g_e[idx] = v;
    atomicMax(&g_menc[dst * NH + hh], fenc(v));
}

__global__ void k_eexp() {
    int idx = blockIdx.x * 256 + threadIdx.x;
    if (idx >= ETOT * NH) return;
    int e = idx >> 3, hh = idx & 7;
    int dst = g_dstC[e];
    float m = fdec(g_menc[dst * NH + hh]);
    float ee = expf(g_e[idx] - m);
    g_e[idx] = ee;
    atomicAdd(&g_den[dst * NH + hh], ee);
}

// ---------------- aggregate x rows: y[n,h,f] = sum_e alpha[e,h] X[src,f] ---
__global__ void __launch_bounds__(128) k_aggx(const float* __restrict__ Xext, int xsel) {
    const float* X = (xsel == 1) ? g_x1 : Xext;
    int n = blockIdx.x;
    int f = threadIdx.x;
    float inv[NH];
    #pragma unroll
    for (int h = 0; h < NH; h++)
        inv[h] = 1.f / (g_den[n * NH + h] + 1e-16f);
    float acc[NH] = {};
    int e0 = g_off[n], e1 = g_off[n + 1];
    for (int j = e0; j < e1; j++) {
        int s   = g_srcS[j];
        int eid = g_eidS[j];
        float xv = X[(size_t)s * FMD + f];
        const float* er = g_e + (size_t)eid * NH;
        #pragma unroll
        for (int h = 0; h < NH; h++)
            acc[h] += er[h] * xv;
    }
    float* yr = g_h + (size_t)n * HCOLS + f;
    #pragma unroll
    for (int h = 0; h < NH; h++)
        yr[h * FMD] = acc[h] * inv[h];
}

// ---------------- tf32 tensor-core GEMM ------------------------------------
// C[M,Nn] = A[M,K] * B'[K,Nn]   (fp32 accumulate, tf32 operands)
// ASEL : 0 = ext A, 1 = g_h, 2 = dual [g_x1 | g_x2] along K (stride 128 each)
// BMODE: 0 = NT (B is [Nn,K] row-major) ; 1 = W-permuted NN (Nn==128):
//        B'[gk][col] = W[gk&127][(gk>>7)*128 + col]
// MODE : 0 = plain store ; 1 = +bias, route circ/mir into d_out ;
//        2 = relu(v*0.125 + bias) -> g_x1/g_x2 (osel)
template <int ASEL, int BMODE, int MODE>
__global__ void __launch_bounds__(256, 2) gemm_tc(
    const float* __restrict__ A, const float* __restrict__ B,
    const float* __restrict__ bias, float* __restrict__ C,
    int M, int Nn, int K, int osel)
{
    __shared__ unsigned sA[BM * SAST];
    __shared__ unsigned sB[BK * SBST];

    int tid  = threadIdx.x;
    int lane = tid & 31;
    int w    = tid >> 5;
    int warp_m = w & 1;        // 2 m-warps  (64 rows each)
    int warp_n = w >> 1;       // 4 n-warps  (32 cols each)
    int m0 = blockIdx.x * BM, n0 = blockIdx.y * BN;

    const float* Ap = (ASEL == 1) ? g_h : A;

    float acc[4][4][4];
    #pragma unroll
    for (int i = 0; i < 4; i++)
        #pragma unroll
        for (int j = 0; j < 4; j++)
            #pragma unroll
            for (int q = 0; q < 4; q++) acc[i][j][q] = 0.f;

    for (int kc = 0; kc < K; kc += BK) {
        // ---- stage A (tf32) ----
        #pragma unroll
        for (int p = 0; p < 4; p++) {
            int r = (tid >> 3) + p * 32;
            int q = (tid & 7) * 4;
            float4 v = make_float4(0.f, 0.f, 0.f, 0.f);
            int m = m0 + r;
            if (m < M) {
                if (ASEL == 2) {
                    int kg = kc + q;
                    const float* src = (kg < FMD)
                        ? (g_x1 + (size_t)m * FMD + kg)
                        : (g_x2 + (size_t)m * FMD + (kg - FMD));
                    v = *(const float4*)src;
                } else {
                    v = *(const float4*)(Ap + (size_t)m * K + kc + q);
                }
            }
            unsigned* dst = &sA[r * SAST + q];
            dst[0] = f2tf(v.x); dst[1] = f2tf(v.y);
            dst[2] = f2tf(v.z); dst[3] = f2tf(v.w);
        }
        // ---- stage B (tf32, k-major rows) ----
        if (BMODE == 1) {
            #pragma unroll
            for (int p = 0; p < 4; p++) {
                int kk = (tid >> 5) + p * 8;
                int c  = (tid & 31) * 4;
                int gk = kc + kk;
                float4 v = *(const float4*)(B + (size_t)(gk & 127) * HCOLS
                                              + ((gk >> 7) << 7) + c);
                unsigned* dst = &sB[kk * SBST + c];
                dst[0] = f2tf(v.x); dst[1] = f2tf(v.y);
                dst[2] = f2tf(v.z); dst[3] = f2tf(v.w);
            }
        } else {
            #pragma unroll
            for (int p = 0; p < 4; p++) {
                int n = (tid >> 3) + p * 32;
                int q = (tid & 7) * 4;
                float4 v = make_float4(0.f, 0.f, 0.f, 0.f);
                if (n0 + n < Nn)
                    v = *(const float4*)(B + (size_t)(n0 + n) * K + kc + q);
                sB[(q + 0) * SBST + n] = f2tf(v.x);
                sB[(q + 1) * SBST + n] = f2tf(v.y);
                sB[(q + 2) * SBST + n] = f2tf(v.z);
                sB[(q + 3) * SBST + n] = f2tf(v.w);
            }
        }
        __syncthreads();

        // ---- compute: 4 k8 steps, 4x4 mma tiles per warp ----
        #pragma unroll
        for (int k8 = 0; k8 < 4; k8++) {
            int kb = k8 * 8;
            unsigned a[4][4], b[4][2];
            #pragma unroll
            for (int mt = 0; mt < 4; mt++) {
                int row = warp_m * 64 + mt * 16 + (lane >> 2);
                const unsigned* base = &sA[row * SAST + kb + (lane & 3)];
                a[mt][0] = base[0];
                a[mt][1] = base[8 * SAST];
                a[mt][2] = base[4];
                a[mt][3] = base[8 * SAST + 4];
            }
            #pragma unroll
            for (int nt = 0; nt < 4; nt++) {
                int n = warp_n * 32 + nt * 8 + (lane >> 2);
                const unsigned* base = &sB[(kb + (lane & 3)) * SBST + n];
                b[nt][0] = base[0];
                b[nt][1] = base[4 * SBST];
            }
            #pragma unroll
            for (int mt = 0; mt < 4; mt++)
                #pragma unroll
                for (int nt = 0; nt < 4; nt++)
                    mma_tf32(acc[mt][nt], a[mt], b[nt]);
        }
        __syncthreads();
    }

    // ---- epilogue ----
    #pragma unroll
    for (int mt = 0; mt < 4; mt++) {
        int rg = m0 + warp_m * 64 + mt * 16 + (lane >> 2);
        #pragma unroll
        for (int nt = 0; nt < 4; nt++) {
            int colg = n0 + warp_n * 32 + nt * 8 + (lane & 3) * 2;
            const float* dv = acc[mt][nt];
            #pragma unroll
            for (int half = 0; half < 2; half++) {
                int m = rg + half * 8;
                if (m >= M) continue;
                float v0 = dv[half * 2 + 0];
                float v1 = dv[half * 2 + 1];
                if (MODE == 0) {
                    if (colg + 1 < Nn) {
                        *(float2*)(C + (size_t)m * Nn + colg) = make_float2(v0, v1);
                    } else if (colg < Nn) {
                        C[(size_t)m * Nn + colg] = v0;
                    }
                } else if (MODE == 1) {
                    v0 += bias[colg];
                    v1 += bias[colg + 1];
                    float* base = (m < CIRCN)
                        ? (C + PQ + (size_t)m * OCD)
                        : (C + PQ + (size_t)CIRCN * OCD + (size_t)(m - CIRCN) * OCD);
                    *(float2*)(base + colg) = make_float2(v0, v1);
                } else {
                    v0 = fmaxf(v0 * 0.125f + bias[colg], 0.f);
                    v1 = fmaxf(v1 * 0.125f + bias[colg + 1], 0.f);
                    float* o = (osel == 1) ? g_x1 : g_x2;
                    *(float2*)(o + (size_t)m * FMD + colg) = make_float2(v0, v1);
                }
            }
        }
    }
}

// ---------------- launch ---------------------------------------------------
extern "C" void kernel_launch(void* const* d_in, const int* in_sizes, int n_in,
                              void* d_out, int out_size)
{
    const float* x   = (const float*)d_in[0];
    const void*  ei  = d_in[1];
    const float* W1  = (const float*)d_in[2];
    const float* as1 = (const float*)d_in[3];
    const float* ad1 = (const float*)d_in[4];
    const float* b1  = (const float*)d_in[5];
    const float* W2  = (const float*)d_in[6];
    const float* as2 = (const float*)d_in[7];
    const float* ad2 = (const float*)d_in[8];
    const float* b2  = (const float*)d_in[9];
    const float* Wc  = (const float*)d_in[10];
    const float* bc  = (const float*)d_in[11];
    float* out = (float*)d_out;

    // edge decode + CSR
    k_detect<<<1, 1>>>((const int*)ei);
    k_decode<<<(ETOT + 255) / 256, 256>>>(ei);
    k_zero_deg<<<(N_NODES + 255) / 256, 256>>>();
    k_count<<<(ETOT + 255) / 256, 256>>>();
    k_scan<<<1, 1024>>>();
    k_scatter<<<(ETOT + 255) / 256, 256>>>();

    int gEH = (ETOT * NH + 255) / 256;
    int gMD = (N_NODES * NH + 255) / 256;
    dim3 gOut((N_NODES + BM - 1) / BM, 1);

    // ---- layer 1 ----
    k_fold<<<HCOLS, 128>>>(W1, as1, ad1);
    k_sd2<<<N_NODES, 64>>>(x, 0);
    k_initmd<<<gMD, 256>>>();
    k_emax<<<gEH, 256>>>();
    k_eexp<<<gEH, 256>>>();
    k_aggx<<<N_NODES, 128>>>(x, 0);
    gemm_tc<1, 1, 2><<<gOut, 256>>>(nullptr, W1, b1, nullptr,
                                    N_NODES, FMD, HCOLS, 1);

    // ---- layer 2 ----
    k_fold<<<HCOLS, 128>>>(W2, as2, ad2);
    k_sd2<<<N_NODES, 64>>>(nullptr, 1);
    k_initmd<<<gMD, 256>>>();
    k_emax<<<gEH, 256>>>();
    k_eexp<<<gEH, 256>>>();
    k_aggx<<<N_NODES, 128>>>(nullptr, 1);
    gemm_tc<1, 1, 2><<<gOut, 256>>>(nullptr, W2, b2, nullptr,
                                    N_NODES, FMD, HCOLS, 2);

    // ---- classifier: emb[n,o] = [x1|x2][n] . Wc[o,:] + bc[o] ----
    gemm_tc<2, 0, 1><<<gOut, 256>>>(nullptr, Wc, bc, out,
                                    N_NODES, OCD, 2 * FMD, 0);

    // ---- P = circ @ mir^T ----
    const float* circ = out + PQ;
    const float* mir  = out + PQ + (size_t)CIRCN * OCD;
    dim3 gP((CIRCN + BM - 1) / BM, (MIRN + BN - 1) / BN);
    gemm_tc<0, 0, 0><<<gP, 256>>>(circ, mir, nullptr, out,
                                  CIRCN, MIRN, FMD, 0);
}

// round 6
// speedup vs baseline: 2.2695x; 1.2167x over previous
#include <cuda_runtime.h>

#define N_NODES 20000
#define FMD 128
#define NH 8
#define OCD 128
#define N_EDGE 160000
#define ETOT 180000           /* E + self loops */
#define CIRCN 504
#define MIRN 19496            /* N - CIRC */
#define PQ 9825984            /* CIRC * MIRN */
#define HCOLS 1024            /* H * FM */

#define BM 128
#define BN 128
#define BK 32
#define SAST 36               /* sA row stride (floats): conflict-free */
#define SBST 136              /* sB k-row stride (floats): conflict-free */

// ---------------- scratch (device globals; no runtime allocation) ----------
__device__ float    g_h[(size_t)N_NODES * HCOLS];   // y buffer
__device__ float    g_s[N_NODES * NH];
__device__ float    g_d[N_NODES * NH];
__device__ int      g_deg[N_NODES];
__device__ int      g_off[N_NODES + 1];
__device__ int      g_cur[N_NODES];
__device__ int      g_srcS[ETOT];
__device__ int      g_srcC[ETOT];
__device__ int      g_dstC[ETOT];
__device__ int      g_is64;
__device__ float    g_x1[N_NODES * FMD];
__device__ float    g_x2[N_NODES * FMD];
__device__ float    g_As[FMD * NH];
__device__ float    g_Ad[FMD * NH];

// fp32 -> tf32 (round to nearest)
__device__ __forceinline__ unsigned f2tf(float f) {
    unsigned r;
    asm("cvt.rna.tf32.f32 %0, %1;" : "=r"(r) : "f"(f));
    return r;
}

// m16n8k8 tf32 MMA, fp32 accumulate
__device__ __forceinline__ void mma_tf32(float* d, const unsigned* a, const unsigned* b) {
    asm("mma.sync.aligned.m16n8k8.row.col.f32.tf32.tf32.f32 "
        "{%0,%1,%2,%3}, {%4,%5,%6,%7}, {%8,%9}, {%0,%1,%2,%3};"
        : "+f"(d[0]), "+f"(d[1]), "+f"(d[2]), "+f"(d[3])
        : "r"(a[0]), "r"(a[1]), "r"(a[2]), "r"(a[3]), "r"(b[0]), "r"(b[1]));
}

// ---------------- edge-index dtype detect -----------------------------------
__global__ void k_detect(const int* __restrict__ ei32) {
    int allz = 1;
    #pragma unroll
    for (int i = 1; i < 32; i += 2)
        if (ei32[i] != 0) allz = 0;
    g_is64 = allz;
}

__global__ void k_zero_deg() {
    int i = blockIdx.x * 256 + threadIdx.x;
    if (i < N_NODES) g_deg[i] = 0;
}

// decode edge list (+self loops) AND count per-dst degree
__global__ void k_decode(const void* __restrict__ ei) {
    int i = blockIdx.x * 256 + threadIdx.x;
    if (i >= ETOT) return;
    int src, dst;
    if (i < N_EDGE) {
        if (g_is64) {
            const long long* p = (const long long*)ei;
            src = (int)p[i];
            dst = (int)p[N_EDGE + i];
        } else {
            const int* p = (const int*)ei;
            src = p[i];
            dst = p[N_EDGE + i];
        }
    } else {
        src = dst = i - N_EDGE;
    }
    g_srcC[i] = src;
    g_dstC[i] = dst;
    atomicAdd(&g_deg[dst], 1);
}

// single-block shuffle scan over degrees -> offsets
__global__ void __launch_bounds__(1024) k_scan() {
    __shared__ int wsum[32];
    __shared__ int carryS;
    int t = threadIdx.x, lane = t & 31, wid = t >> 5;
    if (t == 0) carryS = 0;
    __syncthreads();
    for (int base = 0; base < N_NODES; base += 1024) {
        int i = base + t;
        int orig = (i < N_NODES) ? g_deg[i] : 0;
        int v = orig;
        #pragma unroll
        for (int o = 1; o < 32; o <<= 1) {
            int u = __shfl_up_sync(0xffffffffu, v, o);
            if (lane >= o) v += u;
        }
        if (lane == 31) wsum[wid] = v;
        __syncthreads();
        if (wid == 0) {
            int w = wsum[lane];
            #pragma unroll
            for (int o = 1; o < 32; o <<= 1) {
                int u = __shfl_up_sync(0xffffffffu, w, o);
                if (lane >= o) w += u;
            }
            wsum[lane] = w;
        }
        __syncthreads();
        int woff = wid ? wsum[wid - 1] : 0;
        int carry = carryS;
        int excl = carry + woff + v - orig;
        if (i < N_NODES) { g_off[i] = excl; g_cur[i] = excl; }
        int total = wsum[31];
        __syncthreads();
        if (t == 0) carryS = carry + total;
        __syncthreads();
    }
    if (t == 0) g_off[N_NODES] = carryS;
}

__global__ void k_scatter() {
    int i = blockIdx.x * 256 + threadIdx.x;
    if (i >= ETOT) return;
    int pos = atomicAdd(&g_cur[g_dstC[i]], 1);
    g_srcS[pos] = g_srcC[i];
}

// ---------------- folded attention: As[k,h] = sum_f W[k,h*128+f]*as[h,f] ---
__global__ void __launch_bounds__(128) k_fold(
    const float* __restrict__ W,
    const float* __restrict__ as, const float* __restrict__ ad)
{
    int kh = blockIdx.x;
    int k = kh >> 3, h = kh & 7;
    int t = threadIdx.x;
    float wv = W[(size_t)k * HCOLS + h * FMD + t];
    float sa = wv * as[h * FMD + t];
    float sd = wv * ad[h * FMD + t];
    __shared__ float sh[8];
    int lane = t & 31, wid = t >> 5;
    #pragma unroll
    for (int o = 16; o; o >>= 1) {
        sa += __shfl_xor_sync(0xffffffffu, sa, o);
        sd += __shfl_xor_sync(0xffffffffu, sd, o);
    }
    if (lane == 0) { sh[wid] = sa; sh[4 + wid] = sd; }
    __syncthreads();
    if (t == 0) {
        g_As[k * NH + h] = sh[0] + sh[1] + sh[2] + sh[3];
        g_Ad[k * NH + h] = sh[4] + sh[5] + sh[6] + sh[7];
    }
}

// ---------------- s,d = x @ As / x @ Ad ------------------------------------
__global__ void __launch_bounds__(64) k_sd2(const float* __restrict__ Xext, int xsel) {
    const float* X = (xsel == 1) ? g_x1 : Xext;
    int n = blockIdx.x;
    int w = threadIdx.x >> 5, lane = threadIdx.x & 31;
    const float* xr = X + (size_t)n * FMD;
    const float* Av = (w == 0) ? g_As : g_Ad;
    float part[NH] = {};
    #pragma unroll
    for (int kk = 0; kk < 4; kk++) {
        int k = lane + kk * 32;
        float xv = xr[k];
        #pragma unroll
        for (int h = 0; h < NH; h++)
            part[h] += xv * Av[k * NH + h];
    }
    #pragma unroll
    for (int h = 0; h < NH; h++) {
        float v = part[h];
        #pragma unroll
        for (int o = 16; o; o >>= 1)
            v += __shfl_xor_sync(0xffffffffu, v, o);
        part[h] = v;
    }
    if (lane == 0) {
        float* o = (w == 0) ? g_s : g_d;
        #pragma unroll
        for (int h = 0; h < NH; h++) o[n * NH + h] = part[h];
    }
}

// ---------------- fused softmax + aggregation (warp per node) --------------
// y[n,h,f] = sum_e alpha[e,h] * X[src_e, f],   alpha = softmax over dst edges
__global__ void __launch_bounds__(128) k_attagg(const float* __restrict__ Xext, int xsel) {
    const float* X = (xsel == 1) ? g_x1 : Xext;
    int warp = threadIdx.x >> 5, lane = threadIdx.x & 31;
    int n = blockIdx.x * 4 + warp;
    if (n >= N_NODES) return;
    int e0 = g_off[n], e1 = g_off[n + 1];

    // per-head dst term (lanes 0..7)
    float dn = (lane < 8) ? g_d[n * NH + lane] : 0.f;

    // pass 1: online softmax max/denominator per head
    float m = -1e30f, den = 0.f;
    if (lane < 8) {
        for (int j = e0; j < e1; j++) {
            int s = g_srcS[j];
            float v = g_s[s * NH + lane] + dn;
            v = (v > 0.f) ? v : 0.2f * v;
            float mn = fmaxf(m, v);
            den = den * __expf(m - mn) + __expf(v - mn);
            m = mn;
        }
    }
    float inv = 1.f / (den + 1e-16f);

    // pass 2: alpha-weighted gather of X rows
    float4 acc[NH];
    #pragma unroll
    for (int h = 0; h < NH; h++) acc[h] = make_float4(0.f, 0.f, 0.f, 0.f);

    for (int j = e0; j < e1; j++) {
        int s = g_srcS[j];
        float al = 0.f;
        if (lane < 8) {
            float v = g_s[s * NH + lane] + dn;
            v = (v > 0.f) ? v : 0.2f * v;
            al = __expf(v - m) * inv;
        }
        float4 xv = *(const float4*)(X + (size_t)s * FMD + lane * 4);
        #pragma unroll
        for (int h = 0; h < NH; h++) {
            float a = __shfl_sync(0xffffffffu, al, h);
            acc[h].x += a * xv.x;
            acc[h].y += a * xv.y;
            acc[h].z += a * xv.z;
            acc[h].w += a * xv.w;
        }
    }
    float* yr = g_h + (size_t)n * HCOLS + lane * 4;
    #pragma unroll
    for (int h = 0; h < NH; h++)
        *(float4*)(yr + h * FMD) = acc[h];
}

// ---------------- tf32 tensor-core GEMM ------------------------------------
// C[M,Nn] = A[M,K] * B'[K,Nn]   (fp32 accumulate, tf32 operands)
// ASEL : 0 = ext A, 1 = g_h, 2 = dual [g_x1 | g_x2] along K (stride 128 each)
// BMODE: 0 = NT (B is [Nn,K] row-major) ; 1 = W-permuted NN (Nn==128):
//        B'[gk][col] = W[gk&127][(gk>>7)*128 + col]
// MODE : 0 = plain store ; 1 = +bias, route circ/mir into d_out ;
//        2 = relu(v*0.125 + bias) -> g_x1/g_x2 (osel)
template <int ASEL, int BMODE, int MODE>
__global__ void __launch_bounds__(256, 2) gemm_tc(
    const float* __restrict__ A, const float* __restrict__ B,
    const float* __restrict__ bias, float* __restrict__ C,
    int M, int Nn, int K, int osel)
{
    __shared__ unsigned sA[BM * SAST];
    __shared__ unsigned sB[BK * SBST];

    int tid  = threadIdx.x;
    int lane = tid & 31;
    int w    = tid >> 5;
    int warp_m = w & 1;
    int warp_n = w >> 1;
    int m0 = blockIdx.x * BM, n0 = blockIdx.y * BN;

    const float* Ap = (ASEL == 1) ? g_h : A;

    float acc[4][4][4];
    #pragma unroll
    for (int i = 0; i < 4; i++)
        #pragma unroll
        for (int j = 0; j < 4; j++)
            #pragma unroll
            for (int q = 0; q < 4; q++) acc[i][j][q] = 0.f;

    for (int kc = 0; kc < K; kc += BK) {
        #pragma unroll
        for (int p = 0; p < 4; p++) {
            int r = (tid >> 3) + p * 32;
            int q = (tid & 7) * 4;
            float4 v = make_float4(0.f, 0.f, 0.f, 0.f);
            int m = m0 + r;
            if (m < M) {
                if (ASEL == 2) {
                    int kg = kc + q;
                    const float* src = (kg < FMD)
                        ? (g_x1 + (size_t)m * FMD + kg)
                        : (g_x2 + (size_t)m * FMD + (kg - FMD));
                    v = *(const float4*)src;
                } else {
                    v = *(const float4*)(Ap + (size_t)m * K + kc + q);
                }
            }
            unsigned* dst = &sA[r * SAST + q];
            dst[0] = f2tf(v.x); dst[1] = f2tf(v.y);
            dst[2] = f2tf(v.z); dst[3] = f2tf(v.w);
        }
        if (BMODE == 1) {
            #pragma unroll
            for (int p = 0; p < 4; p++) {
                int kk = (tid >> 5) + p * 8;
                int c  = (tid & 31) * 4;
                int gk = kc + kk;
                float4 v = *(const float4*)(B + (size_t)(gk & 127) * HCOLS
                                              + ((gk >> 7) << 7) + c);
                unsigned* dst = &sB[kk * SBST + c];
                dst[0] = f2tf(v.x); dst[1] = f2tf(v.y);
                dst[2] = f2tf(v.z); dst[3] = f2tf(v.w);
            }
        } else {
            #pragma unroll
            for (int p = 0; p < 4; p++) {
                int n = (tid >> 3) + p * 32;
                int q = (tid & 7) * 4;
                float4 v = make_float4(0.f, 0.f, 0.f, 0.f);
                if (n0 + n < Nn)
                    v = *(const float4*)(B + (size_t)(n0 + n) * K + kc + q);
                sB[(q + 0) * SBST + n] = f2tf(v.x);
                sB[(q + 1) * SBST + n] = f2tf(v.y);
                sB[(q + 2) * SBST + n] = f2tf(v.z);
                sB[(q + 3) * SBST + n] = f2tf(v.w);
            }
        }
        __syncthreads();

        #pragma unroll
        for (int k8 = 0; k8 < 4; k8++) {
            int kb = k8 * 8;
            unsigned a[4][4], b[4][2];
            #pragma unroll
            for (int mt = 0; mt < 4; mt++) {
                int row = warp_m * 64 + mt * 16 + (lane >> 2);
                const unsigned* base = &sA[row * SAST + kb + (lane & 3)];
                a[mt][0] = base[0];
                a[mt][1] = base[8 * SAST];
                a[mt][2] = base[4];
                a[mt][3] = base[8 * SAST + 4];
            }
            #pragma unroll
            for (int nt = 0; nt < 4; nt++) {
                int n = warp_n * 32 + nt * 8 + (lane >> 2);
                const unsigned* base = &sB[(kb + (lane & 3)) * SBST + n];
                b[nt][0] = base[0];
                b[nt][1] = base[4 * SBST];
            }
            #pragma unroll
            for (int mt = 0; mt < 4; mt++)
                #pragma unroll
                for (int nt = 0; nt < 4; nt++)
                    mma_tf32(acc[mt][nt], a[mt], b[nt]);
        }
        __syncthreads();
    }

    #pragma unroll
    for (int mt = 0; mt < 4; mt++) {
        int rg = m0 + warp_m * 64 + mt * 16 + (lane >> 2);
        #pragma unroll
        for (int nt = 0; nt < 4; nt++) {
            int colg = n0 + warp_n * 32 + nt * 8 + (lane & 3) * 2;
            const float* dv = acc[mt][nt];
            #pragma unroll
            for (int half = 0; half < 2; half++) {
                int m = rg + half * 8;
                if (m >= M) continue;
                float v0 = dv[half * 2 + 0];
                float v1 = dv[half * 2 + 1];
                if (MODE == 0) {
                    if (colg + 1 < Nn) {
                        *(float2*)(C + (size_t)m * Nn + colg) = make_float2(v0, v1);
                    } else if (colg < Nn) {
                        C[(size_t)m * Nn + colg] = v0;
                    }
                } else if (MODE == 1) {
                    v0 += bias[colg];
                    v1 += bias[colg + 1];
                    float* base = (m < CIRCN)
                        ? (C + PQ + (size_t)m * OCD)
                        : (C + PQ + (size_t)CIRCN * OCD + (size_t)(m - CIRCN) * OCD);
                    *(float2*)(base + colg) = make_float2(v0, v1);
                } else {
                    v0 = fmaxf(v0 * 0.125f + bias[colg], 0.f);
                    v1 = fmaxf(v1 * 0.125f + bias[colg + 1], 0.f);
                    float* o = (osel == 1) ? g_x1 : g_x2;
                    *(float2*)(o + (size_t)m * FMD + colg) = make_float2(v0, v1);
                }
            }
        }
    }
}

// ---------------- launch ---------------------------------------------------
extern "C" void kernel_launch(void* const* d_in, const int* in_sizes, int n_in,
                              void* d_out, int out_size)
{
    const float* x   = (const float*)d_in[0];
    const void*  ei  = d_in[1];
    const float* W1  = (const float*)d_in[2];
    const float* as1 = (const float*)d_in[3];
    const float* ad1 = (const float*)d_in[4];
    const float* b1  = (const float*)d_in[5];
    const float* W2  = (const float*)d_in[6];
    const float* as2 = (const float*)d_in[7];
    const float* ad2 = (const float*)d_in[8];
    const float* b2  = (const float*)d_in[9];
    const float* Wc  = (const float*)d_in[10];
    const float* bc  = (const float*)d_in[11];
    float* out = (float*)d_out;

    // CSR build
    k_zero_deg<<<(N_NODES + 255) / 256, 256>>>();
    k_detect<<<1, 1>>>((const int*)ei);
    k_decode<<<(ETOT + 255) / 256, 256>>>(ei);
    k_scan<<<1, 1024>>>();
    k_scatter<<<(ETOT + 255) / 256, 256>>>();

    dim3 gOut((N_NODES + BM - 1) / BM, 1);
    int gAtt = (N_NODES + 3) / 4;

    // ---- layer 1 ----
    k_fold<<<HCOLS, 128>>>(W1, as1, ad1);
    k_sd2<<<N_NODES, 64>>>(x, 0);
    k_attagg<<<gAtt, 128>>>(x, 0);
    gemm_tc<1, 1, 2><<<gOut, 256>>>(nullptr, W1, b1, nullptr,
                                    N_NODES, FMD, HCOLS, 1);

    // ---- layer 2 ----
    k_fold<<<HCOLS, 128>>>(W2, as2, ad2);
    k_sd2<<<N_NODES, 64>>>(nullptr, 1);
    k_attagg<<<gAtt, 128>>>(nullptr, 1);
    gemm_tc<1, 1, 2><<<gOut, 256>>>(nullptr, W2, b2, nullptr,
                                    N_NODES, FMD, HCOLS, 2);

    // ---- classifier ----
    gemm_tc<2, 0, 1><<<gOut, 256>>>(nullptr, Wc, bc, out,
                                    N_NODES, OCD, 2 * FMD, 0);

    // ---- P = circ @ mir^T ----
    const float* circ = out + PQ;
    const float* mir  = out + PQ + (size_t)CIRCN * OCD;
    dim3 gP((CIRCN + BM - 1) / BM, (MIRN + BN - 1) / BN);
    gemm_tc<0, 0, 0><<<gP, 256>>>(circ, mir, nullptr, out,
                                  CIRCN, MIRN, FMD, 0);
}